// round 16
// baseline (speedup 1.0000x reference)
#include <cuda_runtime.h>
#include <cuda_bf16.h>
#include <stdint.h>

#define B_   8
#define C_   256
#define N_   4096
#define CQ_  32

// ---------------------------------------------------------------------------
// PTX helpers (sm_80/sm_90-class only -- NO tcgen05)
// ---------------------------------------------------------------------------
__device__ __forceinline__ uint32_t smem_u32(const void* p) {
    uint32_t a;
    asm("{ .reg .u64 t; cvta.to.shared.u64 t, %1; cvt.u32.u64 %0, t; }"
        : "=r"(a) : "l"(p));
    return a;
}

#define MBARRIER_INIT(mbar, count) \
    asm volatile("mbarrier.init.shared.b64 [%0], %1;" \
        :: "r"((uint32_t)(mbar)), "r"((uint32_t)(count)) : "memory")
#define MBARRIER_EXPECT_TX(mbar, bytes) \
    asm volatile("mbarrier.arrive.expect_tx.shared.b64 _, [%0], %1;" \
        :: "r"((uint32_t)(mbar)), "r"((uint32_t)(bytes)) : "memory")

#define MBARRIER_WAIT_PARITY(mbar, parity) do {                                   \
    uint32_t _m = (uint32_t)(mbar); uint32_t _p = (uint32_t)(parity);             \
    uint32_t _done;                                                               \
    asm volatile("{\n\t.reg .pred p;\n\t"                                         \
        "mbarrier.try_wait.parity.acquire.cta.shared::cta.b64 p, [%1], %2;\n\t"   \
        "selp.b32 %0, 1, 0, p;\n\t}"                                              \
        : "=r"(_done) : "r"(_m), "r"(_p) : "memory");                             \
    if (!_done) {                                                                 \
        asm volatile("{\n\t.reg .pred P1;\n\t"                                    \
            "WAIT_LOOP_%=:\n\t"                                                   \
            "mbarrier.try_wait.parity.acquire.cta.shared::cta.b64 P1, [%0], %1, 0x989680;\n\t" \
            "@P1 bra.uni WAIT_DONE_%=;\n\t"                                       \
            "bra.uni WAIT_LOOP_%=;\n\t"                                           \
            "WAIT_DONE_%=:\n\t}"                                                  \
            :: "r"(_m), "r"(_p) : "memory");                                      \
    }                                                                             \
} while (0)

#define BULK_G2S(dst, src, bytes, mbar) \
    asm volatile("cp.async.bulk.shared::cluster.global.mbarrier::complete_tx::bytes " \
        "[%0], [%1], %2, [%3];" \
        :: "r"((uint32_t)(dst)), "l"(__cvta_generic_to_global(src)), \
           "r"((uint32_t)(bytes)), "r"((uint32_t)(mbar)) : "memory")

__device__ __forceinline__ void ldsm4(uint32_t r[4], uint32_t addr) {
    asm volatile("ldmatrix.sync.aligned.m8n8.x4.shared.b16 {%0,%1,%2,%3}, [%4];"
        : "=r"(r[0]), "=r"(r[1]), "=r"(r[2]), "=r"(r[3]) : "r"(addr));
}

__device__ __forceinline__ void mma16816(float d[4], const uint32_t a[4],
                                         uint32_t b0, uint32_t b1) {
    asm volatile("mma.sync.aligned.m16n8k16.row.col.f32.bf16.bf16.f32 "
        "{%0,%1,%2,%3}, {%4,%5,%6,%7}, {%8,%9}, {%0,%1,%2,%3};"
        : "+f"(d[0]), "+f"(d[1]), "+f"(d[2]), "+f"(d[3])
        : "r"(a[0]), "r"(a[1]), "r"(a[2]), "r"(a[3]), "r"(b0), "r"(b1));
}

__device__ __forceinline__ uint32_t pack_bf16x2(float hi, float lo) {
    uint32_t r;
    asm("cvt.rn.satfinite.bf16x2.f32 %0, %1, %2;" : "=r"(r) : "f"(hi), "f"(lo));
    return r;
}

// ---------------------------------------------------------------------------
// Gmem scratch (round-7 layouts)
// ---------------------------------------------------------------------------
__device__ __align__(16) unsigned char g_qh[(size_t)B_ * 64 * 8192];
__device__ __align__(16) unsigned char g_kh[(size_t)B_ * 32 * 16384];
__device__ __align__(16) unsigned char g_vh[(size_t)B_ * 32 * 65536];
__device__ __align__(16) unsigned char g_xh[(size_t)B_ * 16 * 4 * 32768];
__device__ __align__(16) unsigned char g_xl[(size_t)B_ * 16 * 4 * 32768];
__device__ __align__(16) unsigned char g_wc[(size_t)5 * 4 * 16384];

// ---------------------------------------------------------------------------
// xcvt (+ fused wcvt plane): grid (4 kc, 33, 8 b), 256 threads, 6 CTAs/SM.
// (round-15, unchanged)
// ---------------------------------------------------------------------------
#define XC_STRIDE 72
#define XC_SMEM   (2 * 128 * XC_STRIDE * 2)

__global__ __launch_bounds__(256, 6)
void xcvt_kernel(const float* __restrict__ x,
                 const float* __restrict__ wq, const float* __restrict__ wk,
                 const float* __restrict__ wv)
{
    extern __shared__ __align__(16) unsigned char xsm[];
    const int kc = blockIdx.x;
    const int nt = blockIdx.y;
    const int b  = blockIdx.z;
    const int tid = threadIdx.x;

    if (nt == 32) {
        if (b >= 5) return;
        const int mt = b;
        unsigned char* base = g_wc + (size_t)(mt * 4 + kc) * 16384;
#pragma unroll
        for (int it = 0; it < 2; it++) {
            int lin = tid + 256 * it;
            int row = lin >> 3;
            int g   = lin & 7;
            int ck  = kc * 64 + g * 8;
            const float* wp = (mt == 0)
                ? (row < 32 ? &wq[row * 256 + ck] : &wk[(row - 32) * 256 + ck])
                : &wv[(size_t)((mt - 1) * 64 + row) * 256 + ck];
            float4 v0 = *(const float4*)wp;
            float4 v1 = *(const float4*)(wp + 4);
            float fv[8] = {v0.x, v0.y, v0.z, v0.w, v1.x, v1.y, v1.z, v1.w};
            union { uint4 u; __nv_bfloat16 h[8]; } ph, pl;
#pragma unroll
            for (int j = 0; j < 8; j++) {
                ph.h[j] = __float2bfloat16(fv[j]);
                pl.h[j] = __float2bfloat16(fv[j] - __bfloat162float(ph.h[j]));
            }
            uint32_t off = row * 128 + ((g ^ (row & 7)) << 4);
            *(uint4*)(base + off)        = ph.u;
            *(uint4*)(base + 8192 + off) = pl.u;
        }
        return;
    }

    __nv_bfloat16* smh = (__nv_bfloat16*)xsm;
    __nv_bfloat16* sml = smh + 128 * XC_STRIDE;
    const int c0g = kc * 64;
    const int n0g = nt * 128;

#pragma unroll
    for (int it = 0; it < 2; it++) {
        int lin = tid + 256 * it;
        int c4  = lin >> 5;
        int f4  = lin & 31;
        int c0  = c4 * 4;
        float4 v[4];
#pragma unroll
        for (int r = 0; r < 4; r++)
            v[r] = *(const float4*)&x[((size_t)b * C_ + c0g + c0 + r) * N_ + n0g + f4 * 4];
#pragma unroll
        for (int nn = 0; nn < 4; nn++) {
            int n = f4 * 4 + nn;
            float fv[4] = {nn == 0 ? v[0].x : nn == 1 ? v[0].y : nn == 2 ? v[0].z : v[0].w,
                           nn == 0 ? v[1].x : nn == 1 ? v[1].y : nn == 2 ? v[1].z : v[1].w,
                           nn == 0 ? v[2].x : nn == 1 ? v[2].y : nn == 2 ? v[2].z : v[2].w,
                           nn == 0 ? v[3].x : nn == 1 ? v[3].y : nn == 2 ? v[3].z : v[3].w};
            __nv_bfloat16 h[4], l[4];
#pragma unroll
            for (int r = 0; r < 4; r++) {
                h[r] = __float2bfloat16(fv[r]);
                l[r] = __float2bfloat16(fv[r] - __bfloat162float(h[r]));
            }
            *(uint2*)&smh[n * XC_STRIDE + c0] = *(uint2*)h;
            *(uint2*)&sml[n * XC_STRIDE + c0] = *(uint2*)l;
        }
    }
    __syncthreads();

    const size_t base = (((size_t)b * 16 + (nt >> 1)) * 4 + kc) * 32768
                      + (size_t)(nt & 1) * 16384;
#pragma unroll
    for (int it = 0; it < 4; it++) {
        int id = tid + 256 * it;
        int n  = id >> 3;
        int g  = id & 7;
        uint32_t off = n * 128 + ((g ^ (n & 7)) << 4);
        *(uint4*)(g_xh + base + off) = *(uint4*)&smh[n * XC_STRIDE + g * 8];
        *(uint4*)(g_xl + base + off) = *(uint4*)&sml[n * XC_STRIDE + g * 8];
    }
}

// ---------------------------------------------------------------------------
// proj_all: q/k = 3-term hi/lo (2-stage); v = 2-term, 3-STAGE pipeline.
// grid (32 nt, 5 mt, 8 b), 256 threads, 2 CTAs/SM.
// v smem: W stages at 0,16K,32K; x_hi stages at 48K,64K,80K (3 x 32KB total)
// qk smem: W 2x16K at 0; x hi/lo 2x32K at 32K (as before)
// ---------------------------------------------------------------------------
#define PW_OFF   0u
#define PX_OFF   32768u
#define VX_OFF   49152u
#define PB_OFF   98304u
#define PMB_OFF  98560u
#define P_SMEM   98592

__global__ __launch_bounds__(256, 2)
void proj_all_kernel(const float* __restrict__ bq, const float* __restrict__ bk,
                     const float* __restrict__ bv)
{
    extern __shared__ __align__(1024) unsigned char psm[];
    const uint32_t sb = smem_u32(psm);
    const uint32_t mb0 = sb + PMB_OFF;
    const uint32_t mb1 = mb0 + 8;

    const int tid  = threadIdx.x;
    const int lane = tid & 31;
    const int w    = tid >> 5;
    const int nt   = blockIdx.x;
    const int mt   = blockIdx.y;
    const int b    = blockIdx.z;
    const int gr   = lane >> 2;
    const int tc   = lane & 3;
    const bool is_v = (mt != 0);

    float* sBias = (float*)(psm + PB_OFF);

    if (tid == 0) {
        MBARRIER_INIT(mb0, 1);
        MBARRIER_INIT(mb1, 1);
        MBARRIER_INIT(mb0 + 16, 1);
    }
    if (tid < 64) {
        sBias[tid] = (mt == 0) ? (tid < 32 ? bq[tid] : bk[tid - 32])
                               : bv[(mt - 1) * 64 + tid];
    }
    __syncthreads();

    const int xnt  = nt >> 1;
    const size_t xoff = (size_t)(nt & 1) * 16384;
    const size_t xbase = ((size_t)b * 16 + xnt) * 4 * 32768;
    const unsigned char* wbase = g_wc + (size_t)mt * 4 * 16384;

    if (tid == 0) {
        if (is_v) {
            // prologue: chunks 0,1,2 into stages 0,1,2
#pragma unroll
            for (int s = 0; s < 3; s++) {
                MBARRIER_EXPECT_TX(mb0 + 8 * s, 32768);
                BULK_G2S(sb + (uint32_t)s * 16384,
                         wbase + (size_t)s * 16384, 16384, mb0 + 8 * s);
                BULK_G2S(sb + VX_OFF + (uint32_t)s * 16384,
                         g_xh + xbase + (size_t)s * 32768 + xoff, 16384, mb0 + 8 * s);
            }
        } else {
            MBARRIER_EXPECT_TX(mb0, 49152);
            BULK_G2S(sb + PW_OFF, wbase, 16384, mb0);
            BULK_G2S(sb + PX_OFF, g_xh + xbase + xoff, 16384, mb0);
            BULK_G2S(sb + PX_OFF + 16384, g_xl + xbase + xoff, 16384, mb0);
        }
    }

    float acc[8][4];
#pragma unroll
    for (int i = 0; i < 8; i++)
#pragma unroll
        for (int j = 0; j < 4; j++) acc[i][j] = 0.f;

    const int mrow = (w >> 1) * 16;
    const int nwp  = (w & 1) * 64;

    for (int c = 0; c < 4; c++) {
        if (c > 0) __syncthreads();
        uint32_t wst, xst;
        if (is_v) {
            // chunk 3 -> stage 0, issued once chunk-0 compute is done
            if (tid == 0 && c == 1) {
                MBARRIER_EXPECT_TX(mb0, 32768);
                BULK_G2S(sb + 0u, wbase + (size_t)3 * 16384, 16384, mb0);
                BULK_G2S(sb + VX_OFF,
                         g_xh + xbase + (size_t)3 * 32768 + xoff, 16384, mb0);
            }
            const int s3 = (c < 3) ? c : 0;
            MBARRIER_WAIT_PARITY(mb0 + 8 * s3, (c >= 3) ? 1 : 0);
            wst = sb + (uint32_t)s3 * 16384;
            xst = sb + VX_OFF + (uint32_t)s3 * 16384;
        } else {
            if (tid == 0 && c < 3) {
                const uint32_t nmb = ((c + 1) & 1) ? mb1 : mb0;
                const uint32_t nb  = ((c + 1) & 1);
                MBARRIER_EXPECT_TX(nmb, 49152);
                BULK_G2S(sb + PW_OFF + nb * 16384,
                         wbase + (size_t)(c + 1) * 16384, 16384, nmb);
                BULK_G2S(sb + PX_OFF + nb * 32768,
                         g_xh + xbase + (size_t)(c + 1) * 32768 + xoff, 16384, nmb);
                BULK_G2S(sb + PX_OFF + nb * 32768 + 16384,
                         g_xl + xbase + (size_t)(c + 1) * 32768 + xoff, 16384, nmb);
            }
            MBARRIER_WAIT_PARITY((c & 1) ? mb1 : mb0, (c >> 1) & 1);
            wst = sb + PW_OFF + (c & 1) * 16384;
            xst = sb + PX_OFF + (c & 1) * 32768;
        }

        uint32_t Ahi[4][4], Alo[4][4];
        {
            int row = mrow + (lane & 15);
            int sw  = row & 7;
            uint32_t rb = wst + row * 128;
#pragma unroll
            for (int k16 = 0; k16 < 4; k16++) {
                int g = 2 * k16 + (lane >> 4);
                ldsm4(Ahi[k16], rb + ((g ^ sw) << 4));
                ldsm4(Alo[k16], rb + 8192 + ((g ^ sw) << 4));
            }
        }

        const uint32_t xh = xst;
        const uint32_t xl = xst + 16384;
#pragma unroll
        for (int nb = 0; nb < 8; nb++) {
            uint32_t Bh[8], Bl[8];
            int row = nwp + nb * 8 + (lane & 7);
            int sw  = row & 7;
            int ga  = lane >> 3;
            ldsm4(Bh,     xh + row * 128 + ((ga ^ sw) << 4));
            ldsm4(Bh + 4, xh + row * 128 + (((4 + ga) ^ sw) << 4));
            if (!is_v) {
                ldsm4(Bl,     xl + row * 128 + ((ga ^ sw) << 4));
                ldsm4(Bl + 4, xl + row * 128 + (((4 + ga) ^ sw) << 4));
            }
#pragma unroll
            for (int k16 = 0; k16 < 4; k16++) {
                mma16816(acc[nb], Ahi[k16], Bh[2 * k16], Bh[2 * k16 + 1]);
                mma16816(acc[nb], Alo[k16], Bh[2 * k16], Bh[2 * k16 + 1]);
                if (!is_v)
                    mma16816(acc[nb], Ahi[k16], Bl[2 * k16], Bl[2 * k16 + 1]);
            }
        }
    }
    __syncthreads();

    float* st = (float*)(psm + (is_v ? VX_OFF : PX_OFF));
#pragma unroll
    for (int nb = 0; nb < 8; nb++) {
        int ncol = nwp + nb * 8 + tc * 2;
        *(float2*)&st[(mrow + gr) * 132 + ncol]     = make_float2(acc[nb][0], acc[nb][1]);
        *(float2*)&st[(mrow + gr + 8) * 132 + ncol] = make_float2(acc[nb][2], acc[nb][3]);
    }
    __syncthreads();

    if (mt == 0) {
#pragma unroll
        for (int it = 0; it < 8; it++) {
            int id    = tid + 256 * it;
            int which = id >> 10;
            int m2    = id & 1023;
            int nrow  = m2 >> 3;
            int g     = m2 & 7;
            int o0    = (g & 3) * 8;
            bool islo = g >= 4;
            union { uint4 u; __nv_bfloat16 h[8]; } pk;
#pragma unroll
            for (int j = 0; j < 8; j++) {
                float v = st[(which * 32 + o0 + j) * 132 + nrow]
                        + sBias[which * 32 + o0 + j];
                __nv_bfloat16 hi = __float2bfloat16(v);
                pk.h[j] = islo ? __float2bfloat16(v - __bfloat162float(hi)) : hi;
            }
            unsigned char* dst;
            if (which) {
                dst = g_kh + ((size_t)(b * 32 + nt)) * 16384
                    + nrow * 128 + ((g ^ (nrow & 7)) << 4);
            } else {
                int tile = nt * 2 + (nrow >> 6);
                int r    = nrow & 63;
                dst = g_qh + ((size_t)(b * 64 + tile)) * 8192
                    + r * 128 + ((g ^ (r & 7)) << 4);
            }
            *(uint4*)dst = pk.u;
        }
    } else {
        const int ch0 = (mt - 1) * 64;
#pragma unroll
        for (int it = 0; it < 4; it++) {
            int id  = tid + 256 * it;
            int chl = id >> 4;
            int kg  = id & 15;
            int chg = ch0 + chl;
            float bb = sBias[chl];
            union { uint4 u; __nv_bfloat16 h[8]; } pk;
#pragma unroll
            for (int j = 0; j < 8; j++)
                pk.h[j] = __float2bfloat16(st[chl * 132 + kg * 8 + j] + bb);
            *(uint4*)(g_vh + ((size_t)(b * 32 + nt)) * 65536
                      + chg * 256 + ((kg ^ (chg & 7)) << 4)) = pk.u;
        }
    }
}

// ---------------------------------------------------------------------------
// Attention: mma.sync flash attention (round-12/13, byte-identical, protected)
// ---------------------------------------------------------------------------
#define SQ_  0u
#define SK_  8192u
#define SV_  40960u
#define SP0_ 172032u
#define SP1_ 189440u
#define SL_  206848u
#define SMB_ 207104u
#define SMEM_TOTAL 207136

__global__ __launch_bounds__(512, 1)
void attn_kernel(const float* __restrict__ x,
                 const float* __restrict__ gamma,
                 float* __restrict__ y)
{
    extern __shared__ __align__(16) unsigned char smem[];
    const uint32_t sb = smem_u32(smem);
    const int tid  = threadIdx.x;
    const int lane = tid & 31;
    const int w    = tid >> 5;
    const int b    = blockIdx.y;
    const int qt   = blockIdx.x;
    const int ib   = w >> 3;
    const int qd   = w & 7;
    const int gr   = lane >> 2;
    const int tc   = lane & 3;

    if (tid < 64) *(float*)(smem + SL_ + tid * 4) = 0.f;
    if (tid == 0) {
        MBARRIER_INIT(sb + SMB_ + 0, 1);
        MBARRIER_INIT(sb + SMB_ + 8, 1);
    }
    __syncthreads();

    const unsigned char* gq  = g_qh + ((size_t)(b * 64 + qt)) * 8192;
    const unsigned char* gk0 = g_kh + ((size_t)b * 32) * 16384;
    const unsigned char* gv0 = g_vh + ((size_t)b * 32) * 65536;

    if (tid == 0) {
        MBARRIER_EXPECT_TX(sb + SMB_ + 0, 8192 + 16384 + 65536);
        BULK_G2S(sb + SQ_, gq, 8192, sb + SMB_ + 0);
        BULK_G2S(sb + SK_, gk0, 16384, sb + SMB_ + 0);
        BULK_G2S(sb + SV_, gv0, 65536, sb + SMB_ + 0);
        MBARRIER_EXPECT_TX(sb + SMB_ + 8, 16384 + 65536);
        BULK_G2S(sb + SK_ + 16384, gk0 + 16384, 16384, sb + SMB_ + 8);
        BULK_G2S(sb + SV_ + 65536, gv0 + 65536, 65536, sb + SMB_ + 8);
    }

    float accs[8][4];
#pragma unroll
    for (int i = 0; i < 8; i++)
#pragma unroll
        for (int j = 0; j < 4; j++) accs[i][j] = 0.f;

    uint32_t Qa[2][4][4];
    float ls[2][2] = {{0.f, 0.f}, {0.f, 0.f}};

    const int rowp0  = ib * 32 + (lane & 15);
    const int chbase = qd * 32 + ((lane >> 4) << 3) + (lane & 7);
    const int gbit   = (lane >> 3) & 1;

    for (int jt = 0; jt < 32; jt++) {
        const int buf = jt & 1;
        const uint32_t pbuf = buf ? SP1_ : SP0_;
        const uint32_t vbase = sb + SV_ + buf * 65536;

        MBARRIER_WAIT_PARITY(sb + SMB_ + 8 * buf, (jt >> 1) & 1);

        if (jt == 0) {
#pragma unroll
            for (int mb = 0; mb < 2; mb++) {
                int row = ib * 32 + mb * 16 + (lane & 15);
#pragma unroll
                for (int c = 0; c < 4; c++) {
                    int g = 2 * c + (lane >> 4);
                    ldsm4(Qa[mb][c], sb + SQ_ + row * 128 + ((g ^ (row & 7)) << 4));
                }
            }
        }

        uint32_t vbp[2][8];
        {
            int g0 = gbit;
#pragma unroll
            for (int h = 0; h < 2; h++) {
                int ch = chbase + h * 16;
                ldsm4(vbp[0] + 4 * h, vbase + ch * 256 + ((g0 ^ (ch & 7)) << 4));
            }
        }

        const uint32_t kbase = sb + SK_ + buf * 16384;
        uint32_t kb0[8], kb1[8];
        {
            int j0 = qd * 16 + (lane & 7);
            int j1 = j0 + 8;
            int ga = (lane >> 3), gb = 4 + (lane >> 3);
            ldsm4(kb0,     kbase + j0 * 128 + ((ga ^ (j0 & 7)) << 4));
            ldsm4(kb0 + 4, kbase + j0 * 128 + ((gb ^ (j0 & 7)) << 4));
            ldsm4(kb1,     kbase + j1 * 128 + ((ga ^ (j1 & 7)) << 4));
            ldsm4(kb1 + 4, kbase + j1 * 128 + ((gb ^ (j1 & 7)) << 4));
        }
#pragma unroll
        for (int mb = 0; mb < 2; mb++) {
            float d0[4] = {0.f, 0.f, 0.f, 0.f};
            float d1[4] = {0.f, 0.f, 0.f, 0.f};
            mma16816(d0, Qa[mb][0], kb0[0], kb0[1]);
            mma16816(d0, Qa[mb][1], kb0[2], kb0[3]);
            mma16816(d1, Qa[mb][0], kb1[0], kb1[1]);
            mma16816(d1, Qa[mb][1], kb1[2], kb1[3]);
            mma16816(d0, Qa[mb][0], kb0[4], kb0[5]);
            mma16816(d0, Qa[mb][1], kb0[6], kb0[7]);
            mma16816(d1, Qa[mb][0], kb1[4], kb1[5]);
            mma16816(d1, Qa[mb][1], kb1[6], kb1[7]);
            mma16816(d0, Qa[mb][2], kb0[0], kb0[1]);
            mma16816(d0, Qa[mb][3], kb0[2], kb0[3]);
            mma16816(d1, Qa[mb][2], kb1[0], kb1[1]);
            mma16816(d1, Qa[mb][3], kb1[2], kb1[3]);

            int r0 = ib * 32 + mb * 16 + gr;
#pragma unroll
            for (int q2 = 0; q2 < 2; q2++) {
                float* d = q2 ? d1 : d0;
                float e0 = __expf(d[0]), e1 = __expf(d[1]);
                float e2 = __expf(d[2]), e3 = __expf(d[3]);
                ls[mb][0] += e0 + e1;
                ls[mb][1] += e2 + e3;
                int colb = (qd * 16 + q2 * 8 + tc * 2) * 2;
                *(uint32_t*)(smem + pbuf + r0 * 272 + colb)       = pack_bf16x2(e1, e0);
                *(uint32_t*)(smem + pbuf + (r0 + 8) * 272 + colb) = pack_bf16x2(e3, e2);
            }
        }
        __syncthreads();

        if (tid == 0 && jt >= 1 && jt < 31) {
            const int nb = (jt + 1) & 1;
            MBARRIER_EXPECT_TX(sb + SMB_ + 8 * nb, 16384 + 65536);
            BULK_G2S(sb + SK_ + nb * 16384, gk0 + (size_t)(jt + 1) * 16384,
                     16384, sb + SMB_ + 8 * nb);
            BULK_G2S(sb + SV_ + nb * 65536, gv0 + (size_t)(jt + 1) * 65536,
                     65536, sb + SMB_ + 8 * nb);
        }

        uint32_t Pa0[2][4], Pa1[2][4];
        {
            int cb2 = ((lane >> 4) * 8) * 2;
            ldsm4(Pa0[0], sb + pbuf + rowp0 * 272 + cb2);
            ldsm4(Pa1[0], sb + pbuf + (rowp0 + 16) * 272 + cb2);
        }
#pragma unroll
        for (int kc = 0; kc < 8; kc++) {
            const int cur = kc & 1;
            const int nxt = cur ^ 1;
            if (kc < 7) {
                int cb2 = ((kc + 1) * 16 + (lane >> 4) * 8) * 2;
                ldsm4(Pa0[nxt], sb + pbuf + rowp0 * 272 + cb2);
                ldsm4(Pa1[nxt], sb + pbuf + (rowp0 + 16) * 272 + cb2);
                int gn = (kc + 1) * 2 + gbit;
#pragma unroll
                for (int h = 0; h < 2; h++) {
                    int ch = chbase + h * 16;
                    ldsm4(vbp[nxt] + 4 * h, vbase + ch * 256 + ((gn ^ (ch & 7)) << 4));
                }
            }
#pragma unroll
            for (int h = 0; h < 2; h++) {
                mma16816(accs[2 * h],     Pa0[cur], vbp[cur][4 * h],     vbp[cur][4 * h + 1]);
                mma16816(accs[2 * h + 1], Pa0[cur], vbp[cur][4 * h + 2], vbp[cur][4 * h + 3]);
                mma16816(accs[4 + 2 * h],     Pa1[cur], vbp[cur][4 * h],     vbp[cur][4 * h + 1]);
                mma16816(accs[4 + 2 * h + 1], Pa1[cur], vbp[cur][4 * h + 2], vbp[cur][4 * h + 3]);
            }
        }
    }

#pragma unroll
    for (int mb = 0; mb < 2; mb++) {
        ls[mb][0] += __shfl_xor_sync(0xffffffffu, ls[mb][0], 1);
        ls[mb][0] += __shfl_xor_sync(0xffffffffu, ls[mb][0], 2);
        ls[mb][1] += __shfl_xor_sync(0xffffffffu, ls[mb][1], 1);
        ls[mb][1] += __shfl_xor_sync(0xffffffffu, ls[mb][1], 2);
        if (tc == 0) {
            atomicAdd((float*)(smem + SL_ + (ib * 32 + mb * 16 + gr) * 4), ls[mb][0]);
            atomicAdd((float*)(smem + SL_ + (ib * 32 + mb * 16 + gr + 8) * 4), ls[mb][1]);
        }
    }
    __syncthreads();

    const float gm = gamma[0];
    const int i0 = qt * 64;
#pragma unroll
    for (int mb = 0; mb < 2; mb++) {
        const int r0 = ib * 32 + mb * 16 + gr;
        const float inv0 = 1.0f / *(float*)(smem + SL_ + r0 * 4);
        const float inv8 = 1.0f / *(float*)(smem + SL_ + (r0 + 8) * 4);
#pragma unroll
        for (int nb = 0; nb < 4; nb++) {
            int c = qd * 32 + nb * 8 + tc * 2;
            size_t base0 = ((size_t)b * C_ + c) * N_ + i0;
            size_t base1 = base0 + N_;
            float* a = accs[mb * 4 + nb];
            y[base0 + r0]     = gm * a[0] * inv0 + x[base0 + r0];
            y[base1 + r0]     = gm * a[1] * inv0 + x[base1 + r0];
            y[base0 + r0 + 8] = gm * a[2] * inv8 + x[base0 + r0 + 8];
            y[base1 + r0 + 8] = gm * a[3] * inv8 + x[base1 + r0 + 8];
        }
    }
}

// ---------------------------------------------------------------------------
extern "C" void kernel_launch(void* const* d_in, const int* in_sizes, int n_in,
                              void* d_out, int out_size)
{
    const float* x     = (const float*)d_in[0];
    const float* wq    = (const float*)d_in[1];
    const float* bq    = (const float*)d_in[2];
    const float* wk    = (const float*)d_in[3];
    const float* bk    = (const float*)d_in[4];
    const float* wv    = (const float*)d_in[5];
    const float* bv    = (const float*)d_in[6];
    const float* gamma = (const float*)d_in[7];
    float* y = (float*)d_out;

    cudaFuncSetAttribute(xcvt_kernel,
                         cudaFuncAttributeMaxDynamicSharedMemorySize, XC_SMEM);
    cudaFuncSetAttribute(proj_all_kernel,
                         cudaFuncAttributeMaxDynamicSharedMemorySize, P_SMEM);
    cudaFuncSetAttribute(attn_kernel,
                         cudaFuncAttributeMaxDynamicSharedMemorySize, SMEM_TOTAL);

    xcvt_kernel    <<<dim3(4, 33, B_), 256, XC_SMEM>>>(x, wq, wk, wv);
    proj_all_kernel<<<dim3(32, 5, B_), 256, P_SMEM>>>(bq, bk, bv);
    attn_kernel    <<<dim3(64, B_), 512, SMEM_TOTAL>>>(x, gamma, y);
}

// round 17
// speedup vs baseline: 1.0125x; 1.0125x over previous
#include <cuda_runtime.h>
#include <cuda_bf16.h>
#include <stdint.h>

#define B_   8
#define C_   256
#define N_   4096
#define CQ_  32

// ---------------------------------------------------------------------------
// PTX helpers (sm_80/sm_90-class only -- NO tcgen05)
// ---------------------------------------------------------------------------
__device__ __forceinline__ uint32_t smem_u32(const void* p) {
    uint32_t a;
    asm("{ .reg .u64 t; cvta.to.shared.u64 t, %1; cvt.u32.u64 %0, t; }"
        : "=r"(a) : "l"(p));
    return a;
}

#define MBARRIER_INIT(mbar, count) \
    asm volatile("mbarrier.init.shared.b64 [%0], %1;" \
        :: "r"((uint32_t)(mbar)), "r"((uint32_t)(count)) : "memory")
#define MBARRIER_EXPECT_TX(mbar, bytes) \
    asm volatile("mbarrier.arrive.expect_tx.shared.b64 _, [%0], %1;" \
        :: "r"((uint32_t)(mbar)), "r"((uint32_t)(bytes)) : "memory")

#define MBARRIER_WAIT_PARITY(mbar, parity) do {                                   \
    uint32_t _m = (uint32_t)(mbar); uint32_t _p = (uint32_t)(parity);             \
    uint32_t _done;                                                               \
    asm volatile("{\n\t.reg .pred p;\n\t"                                         \
        "mbarrier.try_wait.parity.acquire.cta.shared::cta.b64 p, [%1], %2;\n\t"   \
        "selp.b32 %0, 1, 0, p;\n\t}"                                              \
        : "=r"(_done) : "r"(_m), "r"(_p) : "memory");                             \
    if (!_done) {                                                                 \
        asm volatile("{\n\t.reg .pred P1;\n\t"                                    \
            "WAIT_LOOP_%=:\n\t"                                                   \
            "mbarrier.try_wait.parity.acquire.cta.shared::cta.b64 P1, [%0], %1, 0x989680;\n\t" \
            "@P1 bra.uni WAIT_DONE_%=;\n\t"                                       \
            "bra.uni WAIT_LOOP_%=;\n\t"                                           \
            "WAIT_DONE_%=:\n\t}"                                                  \
            :: "r"(_m), "r"(_p) : "memory");                                      \
    }                                                                             \
} while (0)

#define BULK_G2S(dst, src, bytes, mbar) \
    asm volatile("cp.async.bulk.shared::cluster.global.mbarrier::complete_tx::bytes " \
        "[%0], [%1], %2, [%3];" \
        :: "r"((uint32_t)(dst)), "l"(__cvta_generic_to_global(src)), \
           "r"((uint32_t)(bytes)), "r"((uint32_t)(mbar)) : "memory")

__device__ __forceinline__ void ldsm4(uint32_t r[4], uint32_t addr) {
    asm volatile("ldmatrix.sync.aligned.m8n8.x4.shared.b16 {%0,%1,%2,%3}, [%4];"
        : "=r"(r[0]), "=r"(r[1]), "=r"(r[2]), "=r"(r[3]) : "r"(addr));
}

__device__ __forceinline__ void mma16816(float d[4], const uint32_t a[4],
                                         uint32_t b0, uint32_t b1) {
    asm volatile("mma.sync.aligned.m16n8k16.row.col.f32.bf16.bf16.f32 "
        "{%0,%1,%2,%3}, {%4,%5,%6,%7}, {%8,%9}, {%0,%1,%2,%3};"
        : "+f"(d[0]), "+f"(d[1]), "+f"(d[2]), "+f"(d[3])
        : "r"(a[0]), "r"(a[1]), "r"(a[2]), "r"(a[3]), "r"(b0), "r"(b1));
}

__device__ __forceinline__ uint32_t pack_bf16x2(float hi, float lo) {
    uint32_t r;
    asm("cvt.rn.satfinite.bf16x2.f32 %0, %1, %2;" : "=r"(r) : "f"(hi), "f"(lo));
    return r;
}

// ---------------------------------------------------------------------------
// Gmem scratch (round-7 layouts)
// ---------------------------------------------------------------------------
__device__ __align__(16) unsigned char g_qh[(size_t)B_ * 64 * 8192];
__device__ __align__(16) unsigned char g_kh[(size_t)B_ * 32 * 16384];
__device__ __align__(16) unsigned char g_vh[(size_t)B_ * 32 * 65536];
__device__ __align__(16) unsigned char g_xh[(size_t)B_ * 16 * 4 * 32768];
__device__ __align__(16) unsigned char g_xl[(size_t)B_ * 16 * 4 * 32768];
__device__ __align__(16) unsigned char g_wc[(size_t)5 * 4 * 16384];

// ---------------------------------------------------------------------------
// xcvt (+ fused wcvt plane): grid (4 kc, 33, 8 b), 256 threads, 6 CTAs/SM.
// (round-15, unchanged)
// ---------------------------------------------------------------------------
#define XC_STRIDE 72
#define XC_SMEM   (2 * 128 * XC_STRIDE * 2)

__global__ __launch_bounds__(256, 6)
void xcvt_kernel(const float* __restrict__ x,
                 const float* __restrict__ wq, const float* __restrict__ wk,
                 const float* __restrict__ wv)
{
    extern __shared__ __align__(16) unsigned char xsm[];
    const int kc = blockIdx.x;
    const int nt = blockIdx.y;
    const int b  = blockIdx.z;
    const int tid = threadIdx.x;

    if (nt == 32) {
        if (b >= 5) return;
        const int mt = b;
        unsigned char* base = g_wc + (size_t)(mt * 4 + kc) * 16384;
#pragma unroll
        for (int it = 0; it < 2; it++) {
            int lin = tid + 256 * it;
            int row = lin >> 3;
            int g   = lin & 7;
            int ck  = kc * 64 + g * 8;
            const float* wp = (mt == 0)
                ? (row < 32 ? &wq[row * 256 + ck] : &wk[(row - 32) * 256 + ck])
                : &wv[(size_t)((mt - 1) * 64 + row) * 256 + ck];
            float4 v0 = *(const float4*)wp;
            float4 v1 = *(const float4*)(wp + 4);
            float fv[8] = {v0.x, v0.y, v0.z, v0.w, v1.x, v1.y, v1.z, v1.w};
            union { uint4 u; __nv_bfloat16 h[8]; } ph, pl;
#pragma unroll
            for (int j = 0; j < 8; j++) {
                ph.h[j] = __float2bfloat16(fv[j]);
                pl.h[j] = __float2bfloat16(fv[j] - __bfloat162float(ph.h[j]));
            }
            uint32_t off = row * 128 + ((g ^ (row & 7)) << 4);
            *(uint4*)(base + off)        = ph.u;
            *(uint4*)(base + 8192 + off) = pl.u;
        }
        return;
    }

    __nv_bfloat16* smh = (__nv_bfloat16*)xsm;
    __nv_bfloat16* sml = smh + 128 * XC_STRIDE;
    const int c0g = kc * 64;
    const int n0g = nt * 128;

#pragma unroll
    for (int it = 0; it < 2; it++) {
        int lin = tid + 256 * it;
        int c4  = lin >> 5;
        int f4  = lin & 31;
        int c0  = c4 * 4;
        float4 v[4];
#pragma unroll
        for (int r = 0; r < 4; r++)
            v[r] = *(const float4*)&x[((size_t)b * C_ + c0g + c0 + r) * N_ + n0g + f4 * 4];
#pragma unroll
        for (int nn = 0; nn < 4; nn++) {
            int n = f4 * 4 + nn;
            float fv[4] = {nn == 0 ? v[0].x : nn == 1 ? v[0].y : nn == 2 ? v[0].z : v[0].w,
                           nn == 0 ? v[1].x : nn == 1 ? v[1].y : nn == 2 ? v[1].z : v[1].w,
                           nn == 0 ? v[2].x : nn == 1 ? v[2].y : nn == 2 ? v[2].z : v[2].w,
                           nn == 0 ? v[3].x : nn == 1 ? v[3].y : nn == 2 ? v[3].z : v[3].w};
            __nv_bfloat16 h[4], l[4];
#pragma unroll
            for (int r = 0; r < 4; r++) {
                h[r] = __float2bfloat16(fv[r]);
                l[r] = __float2bfloat16(fv[r] - __bfloat162float(h[r]));
            }
            *(uint2*)&smh[n * XC_STRIDE + c0] = *(uint2*)h;
            *(uint2*)&sml[n * XC_STRIDE + c0] = *(uint2*)l;
        }
    }
    __syncthreads();

    const size_t base = (((size_t)b * 16 + (nt >> 1)) * 4 + kc) * 32768
                      + (size_t)(nt & 1) * 16384;
#pragma unroll
    for (int it = 0; it < 4; it++) {
        int id = tid + 256 * it;
        int n  = id >> 3;
        int g  = id & 7;
        uint32_t off = n * 128 + ((g ^ (n & 7)) << 4);
        *(uint4*)(g_xh + base + off) = *(uint4*)&smh[n * XC_STRIDE + g * 8];
        *(uint4*)(g_xl + base + off) = *(uint4*)&sml[n * XC_STRIDE + g * 8];
    }
}

// ---------------------------------------------------------------------------
// proj_qk: q/k = 3-term hi/lo split, 2-stage. grid (32, 8), 256 thr, 2 CTA/SM.
// ---------------------------------------------------------------------------
#define PW_OFF   0u
#define PX_OFF   32768u
#define PB_OFF   98304u
#define PMB_OFF  98560u
#define P_SMEM   98592

__global__ __launch_bounds__(256, 2)
void proj_qk_kernel(const float* __restrict__ bq, const float* __restrict__ bk)
{
    extern __shared__ __align__(1024) unsigned char psm[];
    const uint32_t sb = smem_u32(psm);
    const uint32_t mb0 = sb + PMB_OFF;
    const uint32_t mb1 = mb0 + 8;

    const int tid  = threadIdx.x;
    const int lane = tid & 31;
    const int w    = tid >> 5;
    const int nt   = blockIdx.x;
    const int b    = blockIdx.y;
    const int gr   = lane >> 2;
    const int tc   = lane & 3;

    float* sBias = (float*)(psm + PB_OFF);

    if (tid == 0) { MBARRIER_INIT(mb0, 1); MBARRIER_INIT(mb1, 1); }
    if (tid < 64) sBias[tid] = (tid < 32) ? bq[tid] : bk[tid - 32];
    __syncthreads();

    const int xnt  = nt >> 1;
    const size_t xoff = (size_t)(nt & 1) * 16384;
    const size_t xbase = ((size_t)b * 16 + xnt) * 4 * 32768;
    const unsigned char* wbase = g_wc;   // mt = 0

    if (tid == 0) {
        MBARRIER_EXPECT_TX(mb0, 49152);
        BULK_G2S(sb + PW_OFF, wbase, 16384, mb0);
        BULK_G2S(sb + PX_OFF, g_xh + xbase + xoff, 16384, mb0);
        BULK_G2S(sb + PX_OFF + 16384, g_xl + xbase + xoff, 16384, mb0);
    }

    float acc[8][4];
#pragma unroll
    for (int i = 0; i < 8; i++)
#pragma unroll
        for (int j = 0; j < 4; j++) acc[i][j] = 0.f;

    const int mrow = (w >> 1) * 16;
    const int nwp  = (w & 1) * 64;

    for (int c = 0; c < 4; c++) {
        if (c > 0) __syncthreads();
        if (tid == 0 && c < 3) {
            const uint32_t nmb = ((c + 1) & 1) ? mb1 : mb0;
            const uint32_t nb  = ((c + 1) & 1);
            MBARRIER_EXPECT_TX(nmb, 49152);
            BULK_G2S(sb + PW_OFF + nb * 16384, wbase + (size_t)(c + 1) * 16384,
                     16384, nmb);
            BULK_G2S(sb + PX_OFF + nb * 32768,
                     g_xh + xbase + (size_t)(c + 1) * 32768 + xoff, 16384, nmb);
            BULK_G2S(sb + PX_OFF + nb * 32768 + 16384,
                     g_xl + xbase + (size_t)(c + 1) * 32768 + xoff, 16384, nmb);
        }
        MBARRIER_WAIT_PARITY((c & 1) ? mb1 : mb0, (c >> 1) & 1);

        uint32_t Ahi[4][4], Alo[4][4];
        {
            int row = mrow + (lane & 15);
            int sw  = row & 7;
            uint32_t rb = sb + PW_OFF + (c & 1) * 16384 + row * 128;
#pragma unroll
            for (int k16 = 0; k16 < 4; k16++) {
                int g = 2 * k16 + (lane >> 4);
                ldsm4(Ahi[k16], rb + ((g ^ sw) << 4));
                ldsm4(Alo[k16], rb + 8192 + ((g ^ sw) << 4));
            }
        }

        const uint32_t xh = sb + PX_OFF + (c & 1) * 32768;
        const uint32_t xl = xh + 16384;
#pragma unroll
        for (int nb = 0; nb < 8; nb++) {
            uint32_t Bh[8], Bl[8];
            int row = nwp + nb * 8 + (lane & 7);
            int sw  = row & 7;
            int ga  = lane >> 3;
            ldsm4(Bh,     xh + row * 128 + ((ga ^ sw) << 4));
            ldsm4(Bh + 4, xh + row * 128 + (((4 + ga) ^ sw) << 4));
            ldsm4(Bl,     xl + row * 128 + ((ga ^ sw) << 4));
            ldsm4(Bl + 4, xl + row * 128 + (((4 + ga) ^ sw) << 4));
#pragma unroll
            for (int k16 = 0; k16 < 4; k16++) {
                mma16816(acc[nb], Ahi[k16], Bh[2 * k16], Bh[2 * k16 + 1]);
                mma16816(acc[nb], Alo[k16], Bh[2 * k16], Bh[2 * k16 + 1]);
                mma16816(acc[nb], Ahi[k16], Bl[2 * k16], Bl[2 * k16 + 1]);
            }
        }
    }
    __syncthreads();

    float* st = (float*)(psm + PX_OFF);
#pragma unroll
    for (int nb = 0; nb < 8; nb++) {
        int ncol = nwp + nb * 8 + tc * 2;
        *(float2*)&st[(mrow + gr) * 132 + ncol]     = make_float2(acc[nb][0], acc[nb][1]);
        *(float2*)&st[(mrow + gr + 8) * 132 + ncol] = make_float2(acc[nb][2], acc[nb][3]);
    }
    __syncthreads();

#pragma unroll
    for (int it = 0; it < 8; it++) {
        int id    = tid + 256 * it;
        int which = id >> 10;
        int m2    = id & 1023;
        int nrow  = m2 >> 3;
        int g     = m2 & 7;
        int o0    = (g & 3) * 8;
        bool islo = g >= 4;
        union { uint4 u; __nv_bfloat16 h[8]; } pk;
#pragma unroll
        for (int j = 0; j < 8; j++) {
            float v = st[(which * 32 + o0 + j) * 132 + nrow]
                    + sBias[which * 32 + o0 + j];
            __nv_bfloat16 hi = __float2bfloat16(v);
            pk.h[j] = islo ? __float2bfloat16(v - __bfloat162float(hi)) : hi;
        }
        unsigned char* dst;
        if (which) {
            dst = g_kh + ((size_t)(b * 32 + nt)) * 16384
                + nrow * 128 + ((g ^ (nrow & 7)) << 4);
        } else {
            int tile = nt * 2 + (nrow >> 6);
            int r    = nrow & 63;
            dst = g_qh + ((size_t)(b * 64 + tile)) * 8192
                + r * 128 + ((g ^ (r & 7)) << 4);
        }
        *(uint4*)dst = pk.u;
    }
}

// ---------------------------------------------------------------------------
// proj_v: v = 2-term (W hi/lo) x x_hi, 2-stage. grid (32 nt, 4 vi, 8 b),
// 256 threads, 64KB smem -> 3 CTAs/SM (6 warps/SMSP).
// ---------------------------------------------------------------------------
#define PV_W    0u         // 2 x 16KB W stages
#define PV_X    32768u     // 2 x 16KB x_hi stages
#define PV_B    65536u     // bias 256B
#define PV_MB   65792u
#define PV_SMEM 65824

__global__ __launch_bounds__(256, 3)
void proj_v_kernel(const float* __restrict__ bv)
{
    extern __shared__ __align__(1024) unsigned char psm[];
    const uint32_t sb = smem_u32(psm);
    const uint32_t mb0 = sb + PV_MB;
    const uint32_t mb1 = mb0 + 8;

    const int tid  = threadIdx.x;
    const int lane = tid & 31;
    const int w    = tid >> 5;
    const int nt   = blockIdx.x;
    const int vi   = blockIdx.y;     // 0..3 -> channel block
    const int b    = blockIdx.z;
    const int gr   = lane >> 2;
    const int tc   = lane & 3;

    float* sBias = (float*)(psm + PV_B);

    if (tid == 0) { MBARRIER_INIT(mb0, 1); MBARRIER_INIT(mb1, 1); }
    if (tid < 64) sBias[tid] = bv[vi * 64 + tid];
    __syncthreads();

    const int xnt  = nt >> 1;
    const size_t xoff = (size_t)(nt & 1) * 16384;
    const size_t xbase = ((size_t)b * 16 + xnt) * 4 * 32768;
    const unsigned char* wbase = g_wc + (size_t)(vi + 1) * 4 * 16384;

    if (tid == 0) {
        MBARRIER_EXPECT_TX(mb0, 32768);
        BULK_G2S(sb + PV_W, wbase, 16384, mb0);
        BULK_G2S(sb + PV_X, g_xh + xbase + xoff, 16384, mb0);
    }

    float acc[8][4];
#pragma unroll
    for (int i = 0; i < 8; i++)
#pragma unroll
        for (int j = 0; j < 4; j++) acc[i][j] = 0.f;

    const int mrow = (w >> 1) * 16;
    const int nwp  = (w & 1) * 64;

    for (int c = 0; c < 4; c++) {
        if (c > 0) __syncthreads();
        if (tid == 0 && c < 3) {
            const uint32_t nmb = ((c + 1) & 1) ? mb1 : mb0;
            const uint32_t nb  = ((c + 1) & 1);
            MBARRIER_EXPECT_TX(nmb, 32768);
            BULK_G2S(sb + PV_W + nb * 16384, wbase + (size_t)(c + 1) * 16384,
                     16384, nmb);
            BULK_G2S(sb + PV_X + nb * 16384,
                     g_xh + xbase + (size_t)(c + 1) * 32768 + xoff, 16384, nmb);
        }
        MBARRIER_WAIT_PARITY((c & 1) ? mb1 : mb0, (c >> 1) & 1);

        uint32_t Ahi[4][4], Alo[4][4];
        {
            int row = mrow + (lane & 15);
            int sw  = row & 7;
            uint32_t rb = sb + PV_W + (c & 1) * 16384 + row * 128;
#pragma unroll
            for (int k16 = 0; k16 < 4; k16++) {
                int g = 2 * k16 + (lane >> 4);
                ldsm4(Ahi[k16], rb + ((g ^ sw) << 4));
                ldsm4(Alo[k16], rb + 8192 + ((g ^ sw) << 4));
            }
        }

        const uint32_t xh = sb + PV_X + (c & 1) * 16384;
#pragma unroll
        for (int nb = 0; nb < 8; nb++) {
            uint32_t Bh[8];
            int row = nwp + nb * 8 + (lane & 7);
            int sw  = row & 7;
            int ga  = lane >> 3;
            ldsm4(Bh,     xh + row * 128 + ((ga ^ sw) << 4));
            ldsm4(Bh + 4, xh + row * 128 + (((4 + ga) ^ sw) << 4));
#pragma unroll
            for (int k16 = 0; k16 < 4; k16++) {
                mma16816(acc[nb], Ahi[k16], Bh[2 * k16], Bh[2 * k16 + 1]);
                mma16816(acc[nb], Alo[k16], Bh[2 * k16], Bh[2 * k16 + 1]);
            }
        }
    }
    __syncthreads();

    // stage accum (64 x 132 fp32 = 33.8KB) at smem base (buffers dead)
    float* st = (float*)psm;
#pragma unroll
    for (int nb = 0; nb < 8; nb++) {
        int ncol = nwp + nb * 8 + tc * 2;
        *(float2*)&st[(mrow + gr) * 132 + ncol]     = make_float2(acc[nb][0], acc[nb][1]);
        *(float2*)&st[(mrow + gr + 8) * 132 + ncol] = make_float2(acc[nb][2], acc[nb][3]);
    }
    __syncthreads();

    const int ch0 = vi * 64;
#pragma unroll
    for (int it = 0; it < 4; it++) {
        int id  = tid + 256 * it;
        int chl = id >> 4;
        int kg  = id & 15;
        int chg = ch0 + chl;
        float bb = sBias[chl];
        union { uint4 u; __nv_bfloat16 h[8]; } pk;
#pragma unroll
        for (int j = 0; j < 8; j++)
            pk.h[j] = __float2bfloat16(st[chl * 132 + kg * 8 + j] + bb);
        *(uint4*)(g_vh + ((size_t)(b * 32 + nt)) * 65536
                  + chg * 256 + ((kg ^ (chg & 7)) << 4)) = pk.u;
    }
}

// ---------------------------------------------------------------------------
// Attention: mma.sync flash attention (round-12/13, byte-identical, protected)
// ---------------------------------------------------------------------------
#define SQ_  0u
#define SK_  8192u
#define SV_  40960u
#define SP0_ 172032u
#define SP1_ 189440u
#define SL_  206848u
#define SMB_ 207104u
#define SMEM_TOTAL 207136

__global__ __launch_bounds__(512, 1)
void attn_kernel(const float* __restrict__ x,
                 const float* __restrict__ gamma,
                 float* __restrict__ y)
{
    extern __shared__ __align__(16) unsigned char smem[];
    const uint32_t sb = smem_u32(smem);
    const int tid  = threadIdx.x;
    const int lane = tid & 31;
    const int w    = tid >> 5;
    const int b    = blockIdx.y;
    const int qt   = blockIdx.x;
    const int ib   = w >> 3;
    const int qd   = w & 7;
    const int gr   = lane >> 2;
    const int tc   = lane & 3;

    if (tid < 64) *(float*)(smem + SL_ + tid * 4) = 0.f;
    if (tid == 0) {
        MBARRIER_INIT(sb + SMB_ + 0, 1);
        MBARRIER_INIT(sb + SMB_ + 8, 1);
    }
    __syncthreads();

    const unsigned char* gq  = g_qh + ((size_t)(b * 64 + qt)) * 8192;
    const unsigned char* gk0 = g_kh + ((size_t)b * 32) * 16384;
    const unsigned char* gv0 = g_vh + ((size_t)b * 32) * 65536;

    if (tid == 0) {
        MBARRIER_EXPECT_TX(sb + SMB_ + 0, 8192 + 16384 + 65536);
        BULK_G2S(sb + SQ_, gq, 8192, sb + SMB_ + 0);
        BULK_G2S(sb + SK_, gk0, 16384, sb + SMB_ + 0);
        BULK_G2S(sb + SV_, gv0, 65536, sb + SMB_ + 0);
        MBARRIER_EXPECT_TX(sb + SMB_ + 8, 16384 + 65536);
        BULK_G2S(sb + SK_ + 16384, gk0 + 16384, 16384, sb + SMB_ + 8);
        BULK_G2S(sb + SV_ + 65536, gv0 + 65536, 65536, sb + SMB_ + 8);
    }

    float accs[8][4];
#pragma unroll
    for (int i = 0; i < 8; i++)
#pragma unroll
        for (int j = 0; j < 4; j++) accs[i][j] = 0.f;

    uint32_t Qa[2][4][4];
    float ls[2][2] = {{0.f, 0.f}, {0.f, 0.f}};

    const int rowp0  = ib * 32 + (lane & 15);
    const int chbase = qd * 32 + ((lane >> 4) << 3) + (lane & 7);
    const int gbit   = (lane >> 3) & 1;

    for (int jt = 0; jt < 32; jt++) {
        const int buf = jt & 1;
        const uint32_t pbuf = buf ? SP1_ : SP0_;
        const uint32_t vbase = sb + SV_ + buf * 65536;

        MBARRIER_WAIT_PARITY(sb + SMB_ + 8 * buf, (jt >> 1) & 1);

        if (jt == 0) {
#pragma unroll
            for (int mb = 0; mb < 2; mb++) {
                int row = ib * 32 + mb * 16 + (lane & 15);
#pragma unroll
                for (int c = 0; c < 4; c++) {
                    int g = 2 * c + (lane >> 4);
                    ldsm4(Qa[mb][c], sb + SQ_ + row * 128 + ((g ^ (row & 7)) << 4));
                }
            }
        }

        uint32_t vbp[2][8];
        {
            int g0 = gbit;
#pragma unroll
            for (int h = 0; h < 2; h++) {
                int ch = chbase + h * 16;
                ldsm4(vbp[0] + 4 * h, vbase + ch * 256 + ((g0 ^ (ch & 7)) << 4));
            }
        }

        const uint32_t kbase = sb + SK_ + buf * 16384;
        uint32_t kb0[8], kb1[8];
        {
            int j0 = qd * 16 + (lane & 7);
            int j1 = j0 + 8;
            int ga = (lane >> 3), gb = 4 + (lane >> 3);
            ldsm4(kb0,     kbase + j0 * 128 + ((ga ^ (j0 & 7)) << 4));
            ldsm4(kb0 + 4, kbase + j0 * 128 + ((gb ^ (j0 & 7)) << 4));
            ldsm4(kb1,     kbase + j1 * 128 + ((ga ^ (j1 & 7)) << 4));
            ldsm4(kb1 + 4, kbase + j1 * 128 + ((gb ^ (j1 & 7)) << 4));
        }
#pragma unroll
        for (int mb = 0; mb < 2; mb++) {
            float d0[4] = {0.f, 0.f, 0.f, 0.f};
            float d1[4] = {0.f, 0.f, 0.f, 0.f};
            mma16816(d0, Qa[mb][0], kb0[0], kb0[1]);
            mma16816(d0, Qa[mb][1], kb0[2], kb0[3]);
            mma16816(d1, Qa[mb][0], kb1[0], kb1[1]);
            mma16816(d1, Qa[mb][1], kb1[2], kb1[3]);
            mma16816(d0, Qa[mb][0], kb0[4], kb0[5]);
            mma16816(d0, Qa[mb][1], kb0[6], kb0[7]);
            mma16816(d1, Qa[mb][0], kb1[4], kb1[5]);
            mma16816(d1, Qa[mb][1], kb1[6], kb1[7]);
            mma16816(d0, Qa[mb][2], kb0[0], kb0[1]);
            mma16816(d0, Qa[mb][3], kb0[2], kb0[3]);
            mma16816(d1, Qa[mb][2], kb1[0], kb1[1]);
            mma16816(d1, Qa[mb][3], kb1[2], kb1[3]);

            int r0 = ib * 32 + mb * 16 + gr;
#pragma unroll
            for (int q2 = 0; q2 < 2; q2++) {
                float* d = q2 ? d1 : d0;
                float e0 = __expf(d[0]), e1 = __expf(d[1]);
                float e2 = __expf(d[2]), e3 = __expf(d[3]);
                ls[mb][0] += e0 + e1;
                ls[mb][1] += e2 + e3;
                int colb = (qd * 16 + q2 * 8 + tc * 2) * 2;
                *(uint32_t*)(smem + pbuf + r0 * 272 + colb)       = pack_bf16x2(e1, e0);
                *(uint32_t*)(smem + pbuf + (r0 + 8) * 272 + colb) = pack_bf16x2(e3, e2);
            }
        }
        __syncthreads();

        if (tid == 0 && jt >= 1 && jt < 31) {
            const int nb = (jt + 1) & 1;
            MBARRIER_EXPECT_TX(sb + SMB_ + 8 * nb, 16384 + 65536);
            BULK_G2S(sb + SK_ + nb * 16384, gk0 + (size_t)(jt + 1) * 16384,
                     16384, sb + SMB_ + 8 * nb);
            BULK_G2S(sb + SV_ + nb * 65536, gv0 + (size_t)(jt + 1) * 65536,
                     65536, sb + SMB_ + 8 * nb);
        }

        uint32_t Pa0[2][4], Pa1[2][4];
        {
            int cb2 = ((lane >> 4) * 8) * 2;
            ldsm4(Pa0[0], sb + pbuf + rowp0 * 272 + cb2);
            ldsm4(Pa1[0], sb + pbuf + (rowp0 + 16) * 272 + cb2);
        }
#pragma unroll
        for (int kc = 0; kc < 8; kc++) {
            const int cur = kc & 1;
            const int nxt = cur ^ 1;
            if (kc < 7) {
                int cb2 = ((kc + 1) * 16 + (lane >> 4) * 8) * 2;
                ldsm4(Pa0[nxt], sb + pbuf + rowp0 * 272 + cb2);
                ldsm4(Pa1[nxt], sb + pbuf + (rowp0 + 16) * 272 + cb2);
                int gn = (kc + 1) * 2 + gbit;
#pragma unroll
                for (int h = 0; h < 2; h++) {
                    int ch = chbase + h * 16;
                    ldsm4(vbp[nxt] + 4 * h, vbase + ch * 256 + ((gn ^ (ch & 7)) << 4));
                }
            }
#pragma unroll
            for (int h = 0; h < 2; h++) {
                mma16816(accs[2 * h],     Pa0[cur], vbp[cur][4 * h],     vbp[cur][4 * h + 1]);
                mma16816(accs[2 * h + 1], Pa0[cur], vbp[cur][4 * h + 2], vbp[cur][4 * h + 3]);
                mma16816(accs[4 + 2 * h],     Pa1[cur], vbp[cur][4 * h],     vbp[cur][4 * h + 1]);
                mma16816(accs[4 + 2 * h + 1], Pa1[cur], vbp[cur][4 * h + 2], vbp[cur][4 * h + 3]);
            }
        }
    }

#pragma unroll
    for (int mb = 0; mb < 2; mb++) {
        ls[mb][0] += __shfl_xor_sync(0xffffffffu, ls[mb][0], 1);
        ls[mb][0] += __shfl_xor_sync(0xffffffffu, ls[mb][0], 2);
        ls[mb][1] += __shfl_xor_sync(0xffffffffu, ls[mb][1], 1);
        ls[mb][1] += __shfl_xor_sync(0xffffffffu, ls[mb][1], 2);
        if (tc == 0) {
            atomicAdd((float*)(smem + SL_ + (ib * 32 + mb * 16 + gr) * 4), ls[mb][0]);
            atomicAdd((float*)(smem + SL_ + (ib * 32 + mb * 16 + gr + 8) * 4), ls[mb][1]);
        }
    }
    __syncthreads();

    const float gm = gamma[0];
    const int i0 = qt * 64;
#pragma unroll
    for (int mb = 0; mb < 2; mb++) {
        const int r0 = ib * 32 + mb * 16 + gr;
        const float inv0 = 1.0f / *(float*)(smem + SL_ + r0 * 4);
        const float inv8 = 1.0f / *(float*)(smem + SL_ + (r0 + 8) * 4);
#pragma unroll
        for (int nb = 0; nb < 4; nb++) {
            int c = qd * 32 + nb * 8 + tc * 2;
            size_t base0 = ((size_t)b * C_ + c) * N_ + i0;
            size_t base1 = base0 + N_;
            float* a = accs[mb * 4 + nb];
            y[base0 + r0]     = gm * a[0] * inv0 + x[base0 + r0];
            y[base1 + r0]     = gm * a[1] * inv0 + x[base1 + r0];
            y[base0 + r0 + 8] = gm * a[2] * inv8 + x[base0 + r0 + 8];
            y[base1 + r0 + 8] = gm * a[3] * inv8 + x[base1 + r0 + 8];
        }
    }
}

// ---------------------------------------------------------------------------
extern "C" void kernel_launch(void* const* d_in, const int* in_sizes, int n_in,
                              void* d_out, int out_size)
{
    const float* x     = (const float*)d_in[0];
    const float* wq    = (const float*)d_in[1];
    const float* bq    = (const float*)d_in[2];
    const float* wk    = (const float*)d_in[3];
    const float* bk    = (const float*)d_in[4];
    const float* wv    = (const float*)d_in[5];
    const float* bv    = (const float*)d_in[6];
    const float* gamma = (const float*)d_in[7];
    float* y = (float*)d_out;

    cudaFuncSetAttribute(xcvt_kernel,
                         cudaFuncAttributeMaxDynamicSharedMemorySize, XC_SMEM);
    cudaFuncSetAttribute(proj_qk_kernel,
                         cudaFuncAttributeMaxDynamicSharedMemorySize, P_SMEM);
    cudaFuncSetAttribute(proj_v_kernel,
                         cudaFuncAttributeMaxDynamicSharedMemorySize, PV_SMEM);
    cudaFuncSetAttribute(attn_kernel,
                         cudaFuncAttributeMaxDynamicSharedMemorySize, SMEM_TOTAL);

    xcvt_kernel    <<<dim3(4, 33, B_), 256, XC_SMEM>>>(x, wq, wk, wv);
    proj_v_kernel  <<<dim3(32, 4, B_), 256, PV_SMEM>>>(bv);
    proj_qk_kernel <<<dim3(32, B_), 256, P_SMEM>>>(bq, bk);
    attn_kernel    <<<dim3(64, B_), 512, SMEM_TOTAL>>>(x, gamma, y);
}